// round 15
// baseline (speedup 1.0000x reference)
#include <cuda_runtime.h>
#include <cuda_bf16.h>
#include <math.h>
#include <stdint.h>

#define N_ 8192
#define K_ 64
#define CARDN 64
#define BIGF 1e9f
#define EPSV 0.01f
#define INV_EPS 100.0f
#define LOG64 4.1588830833596715f
#define SINK_ITERS 300
#define LOG_ITERS 20
#define FOLD_EVERY 20

#define KSPLIT 8
#define KCHUNK (N_ / KSPLIT)        // 1024
#define KTILES (KCHUNK / 32)        // 32

// ---------------- device scratch (no allocations allowed) ----------------
__device__ float g_Tp[KSPLIT][N_ * K_];  // partial adj@S per K-chunk
__device__ float g_T[N_ * K_];           // adj @ S
__device__ float g_C[K_ * K_];
__device__ float g_D[K_ * K_];           // filtration distance
__device__ float g_pers[K_ * K_];        // raw persistence (pre-MST-mask)
__device__ float g_ws[63];
__device__ int   g_us[63], g_vs[63];
__device__ float g_dgm0[CARDN * 2];
__device__ float g_dgm1[CARDN * 2];
__device__ float g_loss[4];

// =====================================================================
// GEMM1: T = adj @ S with mma.sync m16n8k8 tf32, K-split for occupancy
// =====================================================================

__device__ __forceinline__ float tf32r(float x) {
    uint32_t o;
    asm("cvt.rna.tf32.f32 %0, %1;" : "=r"(o) : "f"(x));
    return __uint_as_float(o);
}

__device__ __forceinline__ void mma8(float* d, const uint32_t* a, uint32_t b0, uint32_t b1) {
    asm volatile(
        "mma.sync.aligned.m16n8k8.row.col.f32.tf32.tf32.f32 "
        "{%0,%1,%2,%3},{%4,%5,%6,%7},{%8,%9},{%0,%1,%2,%3};"
        : "+f"(d[0]), "+f"(d[1]), "+f"(d[2]), "+f"(d[3])
        : "r"(a[0]), "r"(a[1]), "r"(a[2]), "r"(a[3]), "r"(b0), "r"(b1));
}

#define ASTRIDE 36
#define BSTRIDE 72
#define GEMM1_SMEM ((64 * ASTRIDE + 32 * BSTRIDE) * 4)

__global__ void __launch_bounds__(128, 5) gemm1_tc(const float* __restrict__ A,
                                                   const float* __restrict__ S) {
    extern __shared__ float sm[];
    float* As = sm;
    float* Bs = sm + 64 * ASTRIDE;

    int tid = threadIdx.x;
    int lane = tid & 31, w = tid >> 5;
    int wr = w >> 1, wc = w & 1;
    int g = lane >> 2, tig = lane & 3;
    int m0 = blockIdx.x * 64;
    int kbase = blockIdx.y * KCHUNK;

    int rA = tid >> 3, c4A = tid & 7;
    int kB = tid >> 4, cnB = tid & 15;

    const float* Ap = A + (size_t)(m0 + rA) * N_ + kbase + c4A * 4;
    const float* Bp = S + (size_t)(kbase + kB) * 64 + cnB * 4;

    float acc[2][4][4];
#pragma unroll
    for (int mc = 0; mc < 2; mc++)
#pragma unroll
        for (int j = 0; j < 4; j++)
#pragma unroll
            for (int e = 0; e < 4; e++) acc[mc][j][e] = 0.f;

    float4 aPre[4], bPre[4];
#pragma unroll
    for (int i = 0; i < 4; i++) {
        aPre[i] = *(const float4*)(Ap + (size_t)(16 * i) * N_);
        bPre[i] = *(const float4*)(Bp + (size_t)(8 * i) * 64);
    }
#pragma unroll
    for (int i = 0; i < 4; i++) {
        float4 v = aPre[i];
        *(float4*)&As[(rA + 16 * i) * ASTRIDE + c4A * 4] =
            make_float4(tf32r(v.x), tf32r(v.y), tf32r(v.z), tf32r(v.w));
        float4 u = bPre[i];
        *(float4*)&Bs[(kB + 8 * i) * BSTRIDE + cnB * 4] =
            make_float4(tf32r(u.x), tf32r(u.y), tf32r(u.z), tf32r(u.w));
    }
    __syncthreads();

    for (int t = 0; t < KTILES; t++) {
        if (t < KTILES - 1) {
            int k0n = (t + 1) * 32;
#pragma unroll
            for (int i = 0; i < 4; i++) {
                aPre[i] = *(const float4*)(Ap + (size_t)(16 * i) * N_ + k0n);
                bPre[i] = *(const float4*)(Bp + (size_t)(k0n + 8 * i) * 64);
            }
        }
#pragma unroll
        for (int kc = 0; kc < 4; kc++) {
            uint32_t af[2][4];
#pragma unroll
            for (int mc = 0; mc < 2; mc++) {
                const float* ab = As + (wr * 32 + mc * 16 + g) * ASTRIDE + kc * 8 + tig;
                af[mc][0] = __float_as_uint(ab[0]);
                af[mc][1] = __float_as_uint(ab[8 * ASTRIDE]);
                af[mc][2] = __float_as_uint(ab[4]);
                af[mc][3] = __float_as_uint(ab[8 * ASTRIDE + 4]);
            }
#pragma unroll
            for (int j = 0; j < 4; j++) {
                int nb = (wc * 4 + j) * 8 + g;
                const float* bb = Bs + (kc * 8 + tig) * BSTRIDE + nb;
                uint32_t b0 = __float_as_uint(bb[0]);
                uint32_t b1 = __float_as_uint(bb[4 * BSTRIDE]);
                mma8(acc[0][j], af[0], b0, b1);
                mma8(acc[1][j], af[1], b0, b1);
            }
        }
        __syncthreads();
        if (t < KTILES - 1) {
#pragma unroll
            for (int i = 0; i < 4; i++) {
                float4 v = aPre[i];
                *(float4*)&As[(rA + 16 * i) * ASTRIDE + c4A * 4] =
                    make_float4(tf32r(v.x), tf32r(v.y), tf32r(v.z), tf32r(v.w));
                float4 u = bPre[i];
                *(float4*)&Bs[(kB + 8 * i) * BSTRIDE + cnB * 4] =
                    make_float4(tf32r(u.x), tf32r(u.y), tf32r(u.z), tf32r(u.w));
            }
            __syncthreads();
        }
    }

    float* Tp = g_Tp[blockIdx.y];
#pragma unroll
    for (int mc = 0; mc < 2; mc++)
#pragma unroll
        for (int j = 0; j < 4; j++) {
            int row = m0 + wr * 32 + mc * 16 + g;
            int col = wc * 32 + j * 8 + tig * 2;
            *(float2*)&Tp[(size_t)row * 64 + col] =
                make_float2(acc[mc][j][0], acc[mc][j][1]);
            *(float2*)&Tp[(size_t)(row + 8) * 64 + col] =
                make_float2(acc[mc][j][2], acc[mc][j][3]);
        }
}

__global__ void __launch_bounds__(256) reduce_T() {
    int idx = (blockIdx.x * 256 + threadIdx.x) * 4;
    float4 s = *(const float4*)&g_Tp[0][idx];
#pragma unroll
    for (int c = 1; c < KSPLIT; c++) {
        float4 v = *(const float4*)&g_Tp[c][idx];
        s.x += v.x; s.y += v.y; s.z += v.z; s.w += v.w;
    }
    *(float4*)&g_T[idx] = s;
}

// ================= GEMM2: C = S^T @ T =================
__global__ void __launch_bounds__(256) gemm2_kernel(const float* __restrict__ S) {
    int b = blockIdx.x;
    int tid = threadIdx.x;
    int j4 = (tid & 15) * 4;
    int slice = tid >> 4;
    float4 acc = make_float4(0.f, 0.f, 0.f, 0.f);
    for (int k = slice; k < N_; k += 16) {
        float sb = __ldg(S + (size_t)k * 64 + b);
        float4 tv = *(const float4*)&g_T[(size_t)k * 64 + j4];
        acc.x += sb * tv.x; acc.y += sb * tv.y;
        acc.z += sb * tv.z; acc.w += sb * tv.w;
    }
    __shared__ float4 red[256];
    red[tid] = acc;
    __syncthreads();
    if (tid < 64) {
        int g = tid >> 2, comp = tid & 3;
        float v = 0.f;
#pragma unroll
        for (int sl = 0; sl < 16; sl++)
            v += ((const float*)&red[sl * 16 + g])[comp];
        g_C[b * 64 + tid] = v;
    }
}

// ========== finalize D: symmetrize, normalize, zero diagonal ==========
__global__ void __launch_bounds__(1024) finalizeD_kernel() {
    __shared__ float Dsm[4096];
    __shared__ float wred[32];
    __shared__ float mx_s;
    int tid = threadIdx.x;
    int lane = tid & 31, warp = tid >> 5;

    float lmax = -1e30f;
#pragma unroll
    for (int w = 0; w < 4; w++) {
        int p = tid + w * 1024;
        int i = p >> 6, jj = p & 63;
        float cs = 0.5f * (g_C[i * 64 + jj] + g_C[jj * 64 + i]);
        Dsm[p] = cs;
        lmax = fmaxf(lmax, cs);
    }
    for (int o = 16; o; o >>= 1) lmax = fmaxf(lmax, __shfl_xor_sync(~0u, lmax, o));
    if (lane == 0) wred[warp] = lmax;
    __syncthreads();
    if (warp == 0) {
        float v = wred[lane];
        for (int o = 16; o; o >>= 1) v = fmaxf(v, __shfl_xor_sync(~0u, v, o));
        if (lane == 0) mx_s = v;
    }
    __syncthreads();
    float inv = 1.0f / (mx_s + 1e-12f);
#pragma unroll
    for (int w = 0; w < 4; w++) {
        int p = tid + w * 1024;
        int i = p >> 6, jj = p & 63;
        float d = 1.0f - Dsm[p] * inv;
        g_D[p] = (i == jj) ? 0.0f : d;
    }
}

// ========== block 0: Prim MST ; blocks 1..64: death row i = bid-1 ==========
__global__ void __launch_bounds__(64) mstdeath_kernel() {
    __shared__ float Ds[64][65];
    __shared__ float mind[64];
    __shared__ int minu[64];
    int t = threadIdx.x;

    // load full D into smem (64 threads x 64 rows)
    for (int q = 0; q < 64; q++)
        Ds[q][t] = g_D[q * 64 + t];
    __syncthreads();

    if (blockIdx.x == 0) {
        if (t < 32) {
            int lane = t;
            unsigned long long intree = 1ull;
#pragma unroll
            for (int h = 0; h < 2; h++) {
                int v = lane + 32 * h;
                mind[v] = Ds[0][v];
                minu[v] = 0;
            }
            __syncwarp();
            for (int step = 0; step < 63; step++) {
                float bval = BIGF; int bidx = 64;
#pragma unroll
                for (int h = 0; h < 2; h++) {
                    int v = lane + 32 * h;
                    float mv = ((intree >> v) & 1ull) ? BIGF : mind[v];
                    if (mv < bval || (mv == bval && v < bidx)) { bval = mv; bidx = v; }
                }
                for (int o = 16; o; o >>= 1) {
                    float ov = __shfl_xor_sync(~0u, bval, o);
                    int oi = __shfl_xor_sync(~0u, bidx, o);
                    if (ov < bval || (ov == bval && oi < bidx)) { bval = ov; bidx = oi; }
                }
                int vstar = bidx;
                if (lane == 0) { g_ws[step] = bval; g_us[step] = minu[vstar]; g_vs[step] = vstar; }
                intree |= (1ull << vstar);
#pragma unroll
                for (int h = 0; h < 2; h++) {
                    int v = lane + 32 * h;
                    float dv = Ds[vstar][v];
                    if (dv < mind[v]) { mind[v] = dv; minu[v] = vstar; }
                }
                __syncwarp();
            }
        }
    } else {
        int i = blockIdx.x - 1;
        int j = t;
        float pe = -1.0f;
        if (i < j) {
            float mm = BIGF;
#pragma unroll
            for (int k = 0; k < 64; k++) {
                float m2 = fmaxf(Ds[i][k], Ds[j][k]);
                if (k != i && k != j) mm = fminf(mm, m2);
            }
            float dij = Ds[i][j];
            pe = fmaxf(dij, mm) - dij;
        }
        g_pers[i * 64 + j] = pe;
    }
}

// ========== top-64 persistence pairs -> dgm1 ; dgm0 from MST weights ==========
__global__ void __launch_bounds__(1024) topk_kernel() {
    __shared__ float Dsm[4096];
    __shared__ float pers[4096];
    __shared__ unsigned long long msk[64];
    __shared__ float wmax[32];
    __shared__ int widx[32];

    int tid = threadIdx.x;
    int lane = tid & 31, warp = tid >> 5;

    if (tid < 64) {
        g_dgm0[2 * tid] = 0.0f;
        g_dgm0[2 * tid + 1] = (tid < 63) ? g_ws[tid] : 0.0f;
        msk[tid] = 0ull;
    }
    __syncthreads();
    if (tid < 63) {
        atomicOr(&msk[g_us[tid]], 1ull << g_vs[tid]);
        atomicOr(&msk[g_vs[tid]], 1ull << g_us[tid]);
    }
    __syncthreads();

#pragma unroll
    for (int w = 0; w < 4; w++) {
        int p = tid + w * 1024;
        int i = p >> 6, jj = p & 63;
        Dsm[p] = g_D[p];
        float pe = g_pers[p];
        if ((msk[i] >> jj) & 1ull) pe = -1.0f;   // MST edges invalid
        pers[p] = pe;
    }
    __syncthreads();

    // per-warp segment maxima
    {
        float bv = -3e9f; int bi = 1 << 30;
#pragma unroll
        for (int q = 0; q < 4; q++) {
            int p = warp * 128 + q * 32 + lane;
            float v = pers[p];
            if (v > bv || (v == bv && p < bi)) { bv = v; bi = p; }
        }
        for (int o = 16; o; o >>= 1) {
            float ov = __shfl_xor_sync(~0u, bv, o);
            int oi = __shfl_xor_sync(~0u, bi, o);
            if (ov > bv || (ov == bv && oi < bi)) { bv = ov; bi = oi; }
        }
        if (lane == 0) { wmax[warp] = bv; widx[warp] = bi; }
    }
    __syncthreads();

    if (warp == 0) {
        for (int r = 0; r < 64; r++) {
            float v2 = wmax[lane]; int i2 = widx[lane]; int sg = lane;
            for (int o = 16; o; o >>= 1) {
                float ov = __shfl_xor_sync(~0u, v2, o);
                int oi = __shfl_xor_sync(~0u, i2, o);
                int os = __shfl_xor_sync(~0u, sg, o);
                if (ov > v2 || (ov == v2 && oi < i2)) { v2 = ov; i2 = oi; sg = os; }
            }
            if (lane == 0) {
                float b = 0.f, d = 0.f;
                if (v2 > 0.f) { b = Dsm[i2]; d = b + v2; }
                g_dgm1[2 * r] = b;
                g_dgm1[2 * r + 1] = d;
                pers[i2] = -4e9f;
            }
            __syncwarp();
            float nv = -3e9f; int ni = 1 << 30;
#pragma unroll
            for (int q = 0; q < 4; q++) {
                int p = sg * 128 + q * 32 + lane;
                float v = pers[p];
                if (v > nv || (v == nv && p < ni)) { nv = v; ni = p; }
            }
            for (int o = 16; o; o >>= 1) {
                float ov = __shfl_xor_sync(~0u, nv, o);
                int oi = __shfl_xor_sync(~0u, ni, o);
                if (ov > nv || (ov == nv && oi < ni)) { nv = ov; ni = oi; }
            }
            if (lane == 0) { wmax[sg] = nv; widx[sg] = ni; }
            __syncwarp();
        }
    }
}

// ============ Sinkhorn W1: 96 threads, 1 thread/row, K in smem ============
// stride 73 (= 9 mod 32) makes BOTH row and column accesses conflict-free.
// Phase A: 20 log-domain iters (stabilize). Phase B: multiplicative with
// K-refold every 20 iters + convergence early-exit (u,v ~= 1 when converged).
__global__ void __launch_bounds__(96) sinkhorn_kernel(const float* __restrict__ Yb0,
                                                      const float* __restrict__ Yb1,
                                                      const float* __restrict__ Yn0,
                                                      const float* __restrict__ Yn1) {
    __shared__ float Cs[65][73];   // C * INV_EPS
    __shared__ float Ks[65][73];
    __shared__ float Fsh[65], Gsh[65], Ush[65], Vsh[65];
    __shared__ float asum[96];
    __shared__ int notconv;

    int b = blockIdx.x;
    const float* X = (b & 1) ? g_dgm1 : g_dgm0;
    const float* Y = (b == 0) ? Yb0 : (b == 1) ? Yb1 : (b == 2) ? Yn0 : Yn1;
    int t = threadIdx.x;

    for (int idx = t; idx < 65 * 65; idx += 96) {
        int i = idx / 65, j = idx - i * 65;
        float v;
        if (i < 64 && j < 64)
            v = fmaxf(fabsf(X[2 * i] - Y[2 * j]), fabsf(X[2 * i + 1] - Y[2 * j + 1])) * INV_EPS;
        else if (i < 64)
            v = 0.5f * (X[2 * i + 1] - X[2 * i]) * INV_EPS;
        else if (j < 64)
            v = 0.5f * (Y[2 * j + 1] - Y[2 * j]) * INV_EPS;
        else
            v = 0.f;
        Cs[i][j] = v;
    }
    if (t < 65) { Fsh[t] = 0.f; Gsh[t] = 0.f; }
    if (t == 0) notconv = 0;
    __syncthreads();

    int row = t;
    bool act = (t < 65);
    float la = (row == 64) ? LOG64 : 0.f;
    float ela = (row == 64) ? 64.f : 1.f;
    float tF = 0.f, tG = 0.f;

    // ---- phase A: log-domain ----
    for (int it = 0; it < LOG_ITERS; it++) {
        if (act) {
            float s = 0.f;
#pragma unroll 13
            for (int j = 0; j < 65; j++)
                s += __expf(tF + Gsh[j] - Cs[row][j]);
            tF += la - __logf(s);
            Fsh[row] = tF;
        }
        __syncthreads();
        if (act) {
            float s = 0.f;
#pragma unroll 13
            for (int i = 0; i < 65; i++)
                s += __expf(tG + Fsh[i] - Cs[i][row]);
            tG += la - __logf(s);
            Gsh[row] = tG;
        }
        __syncthreads();
    }

    // ---- snapshot K ----
    if (act) {
#pragma unroll 13
        for (int j = 0; j < 65; j++)
            Ks[row][j] = __expf(tF + Gsh[j] - Cs[row][j]);
        Ush[row] = 1.f;
        Vsh[row] = 1.f;
    }
    __syncthreads();

    // ---- phase B: multiplicative with folds + early exit ----
    const int BITERS = SINK_ITERS - LOG_ITERS;
    for (int it = 0; it < BITERS; it++) {
        if (act) {
            float s = 0.f;
#pragma unroll 13
            for (int j = 0; j < 65; j++)
                s += Ks[row][j] * Vsh[j];
            Ush[row] = ela / s;
        }
        __syncthreads();
        if (act) {
            float s = 0.f;
#pragma unroll 13
            for (int i = 0; i < 65; i++)
                s += Ks[i][row] * Ush[i];
            Vsh[row] = ela / s;
        }
        __syncthreads();

        if ((it % FOLD_EVERY) == (FOLD_EVERY - 1) && it != BITERS - 1) {
            if (act) {
                float du = fabsf(Ush[row] - 1.f) + fabsf(Vsh[row] - 1.f);
                if (du > 1e-5f) atomicOr(&notconv, 1);
            }
            __syncthreads();
            int nc = notconv;
            // fold K <- K * u_i * v_j
            if (act) {
                float ur = Ush[row];
#pragma unroll 13
                for (int j = 0; j < 65; j++)
                    Ks[row][j] *= ur * Vsh[j];
            }
            __syncthreads();
            if (act) { Ush[row] = 1.f; Vsh[row] = 1.f; }
            if (t == 0) notconv = 0;
            __syncthreads();
            if (!nc) break;
        }
    }

    // loss = sum P*C ; P_ij = Ks_ij * u_i * v_j ; C = Cs * EPSV
    float acc = 0.f;
    if (act) {
        float ur = Ush[row];
#pragma unroll 13
        for (int j = 0; j < 65; j++)
            acc += Ks[row][j] * Vsh[j] * Cs[row][j];
        acc *= ur * EPSV;
    }
    asum[t] = acc;
    __syncthreads();
    if (t == 0) {
        float s = 0.f;
        for (int q = 0; q < 65; q++) s += asum[q];
        g_loss[b] = s;
    }
}

__global__ void final_kernel(float* out) {
    out[0] = 0.1f * (g_loss[0] + g_loss[1] + g_loss[2] + g_loss[3]);
}

// ---------------- launch ----------------
extern "C" void kernel_launch(void* const* d_in, const int* in_sizes, int n_in,
                              void* d_out, int out_size) {
    const float* adj = (const float*)d_in[0];
    const float* S = (const float*)d_in[1];
    cudaFuncSetAttribute(gemm1_tc, cudaFuncAttributeMaxDynamicSharedMemorySize, GEMM1_SMEM);
    dim3 g1grid(128, KSPLIT);
    gemm1_tc<<<g1grid, 128, GEMM1_SMEM>>>(adj, S);
    reduce_T<<<(N_ * K_ / 4) / 256, 256>>>();
    gemm2_kernel<<<64, 256>>>(S);
    finalizeD_kernel<<<1, 1024>>>();
    mstdeath_kernel<<<65, 64>>>();
    topk_kernel<<<1, 1024>>>();
    sinkhorn_kernel<<<4, 96>>>((const float*)d_in[2], (const float*)d_in[3],
                               (const float*)d_in[4], (const float*)d_in[5]);
    final_kernel<<<1, 1>>>((float*)d_out);
}

// round 16
// speedup vs baseline: 1.3159x; 1.3159x over previous
#include <cuda_runtime.h>
#include <cuda_bf16.h>
#include <math.h>
#include <stdint.h>

#define N_ 8192
#define K_ 64
#define CARDN 64
#define BIGF 1e9f
#define EPSV 0.01f
#define INV_EPS 100.0f
#define LOG64 4.1588830833596715f
#define SINK_ITERS 300
#define LOG_ITERS 20
#define FOLD_EVERY 20

#define KSPLIT 8
#define KCHUNK (N_ / KSPLIT)        // 1024
#define KTILES (KCHUNK / 32)        // 32

// ---------------- device scratch (no allocations allowed) ----------------
__device__ float g_Tp[KSPLIT][N_ * K_];  // partial adj@S per K-chunk
__device__ float g_T[N_ * K_];           // adj @ S
__device__ float g_C[K_ * K_];
__device__ float g_D[K_ * K_];           // filtration distance
__device__ float g_pers[K_ * K_];        // raw persistence (pre-MST-mask)
__device__ float g_ws[63];
__device__ int   g_us[63], g_vs[63];
__device__ float g_dgm0[CARDN * 2];
__device__ float g_dgm1[CARDN * 2];
__device__ float g_loss[4];

// =====================================================================
// GEMM1: T = adj @ S with mma.sync m16n8k8 tf32, K-split for occupancy
// =====================================================================

__device__ __forceinline__ float tf32r(float x) {
    uint32_t o;
    asm("cvt.rna.tf32.f32 %0, %1;" : "=r"(o) : "f"(x));
    return __uint_as_float(o);
}

__device__ __forceinline__ void mma8(float* d, const uint32_t* a, uint32_t b0, uint32_t b1) {
    asm volatile(
        "mma.sync.aligned.m16n8k8.row.col.f32.tf32.tf32.f32 "
        "{%0,%1,%2,%3},{%4,%5,%6,%7},{%8,%9},{%0,%1,%2,%3};"
        : "+f"(d[0]), "+f"(d[1]), "+f"(d[2]), "+f"(d[3])
        : "r"(a[0]), "r"(a[1]), "r"(a[2]), "r"(a[3]), "r"(b0), "r"(b1));
}

#define ASTRIDE 36
#define BSTRIDE 72
#define GEMM1_SMEM ((64 * ASTRIDE + 32 * BSTRIDE) * 4)

__global__ void __launch_bounds__(128, 5) gemm1_tc(const float* __restrict__ A,
                                                   const float* __restrict__ S) {
    extern __shared__ float sm[];
    float* As = sm;
    float* Bs = sm + 64 * ASTRIDE;

    int tid = threadIdx.x;
    int lane = tid & 31, w = tid >> 5;
    int wr = w >> 1, wc = w & 1;
    int g = lane >> 2, tig = lane & 3;
    int m0 = blockIdx.x * 64;
    int kbase = blockIdx.y * KCHUNK;

    int rA = tid >> 3, c4A = tid & 7;
    int kB = tid >> 4, cnB = tid & 15;

    const float* Ap = A + (size_t)(m0 + rA) * N_ + kbase + c4A * 4;
    const float* Bp = S + (size_t)(kbase + kB) * 64 + cnB * 4;

    float acc[2][4][4];
#pragma unroll
    for (int mc = 0; mc < 2; mc++)
#pragma unroll
        for (int j = 0; j < 4; j++)
#pragma unroll
            for (int e = 0; e < 4; e++) acc[mc][j][e] = 0.f;

    float4 aPre[4], bPre[4];
#pragma unroll
    for (int i = 0; i < 4; i++) {
        aPre[i] = *(const float4*)(Ap + (size_t)(16 * i) * N_);
        bPre[i] = *(const float4*)(Bp + (size_t)(8 * i) * 64);
    }
#pragma unroll
    for (int i = 0; i < 4; i++) {
        float4 v = aPre[i];
        *(float4*)&As[(rA + 16 * i) * ASTRIDE + c4A * 4] =
            make_float4(tf32r(v.x), tf32r(v.y), tf32r(v.z), tf32r(v.w));
        float4 u = bPre[i];
        *(float4*)&Bs[(kB + 8 * i) * BSTRIDE + cnB * 4] =
            make_float4(tf32r(u.x), tf32r(u.y), tf32r(u.z), tf32r(u.w));
    }
    __syncthreads();

    for (int t = 0; t < KTILES; t++) {
        if (t < KTILES - 1) {
            int k0n = (t + 1) * 32;
#pragma unroll
            for (int i = 0; i < 4; i++) {
                aPre[i] = *(const float4*)(Ap + (size_t)(16 * i) * N_ + k0n);
                bPre[i] = *(const float4*)(Bp + (size_t)(k0n + 8 * i) * 64);
            }
        }
#pragma unroll
        for (int kc = 0; kc < 4; kc++) {
            uint32_t af[2][4];
#pragma unroll
            for (int mc = 0; mc < 2; mc++) {
                const float* ab = As + (wr * 32 + mc * 16 + g) * ASTRIDE + kc * 8 + tig;
                af[mc][0] = __float_as_uint(ab[0]);
                af[mc][1] = __float_as_uint(ab[8 * ASTRIDE]);
                af[mc][2] = __float_as_uint(ab[4]);
                af[mc][3] = __float_as_uint(ab[8 * ASTRIDE + 4]);
            }
#pragma unroll
            for (int j = 0; j < 4; j++) {
                int nb = (wc * 4 + j) * 8 + g;
                const float* bb = Bs + (kc * 8 + tig) * BSTRIDE + nb;
                uint32_t b0 = __float_as_uint(bb[0]);
                uint32_t b1 = __float_as_uint(bb[4 * BSTRIDE]);
                mma8(acc[0][j], af[0], b0, b1);
                mma8(acc[1][j], af[1], b0, b1);
            }
        }
        __syncthreads();
        if (t < KTILES - 1) {
#pragma unroll
            for (int i = 0; i < 4; i++) {
                float4 v = aPre[i];
                *(float4*)&As[(rA + 16 * i) * ASTRIDE + c4A * 4] =
                    make_float4(tf32r(v.x), tf32r(v.y), tf32r(v.z), tf32r(v.w));
                float4 u = bPre[i];
                *(float4*)&Bs[(kB + 8 * i) * BSTRIDE + cnB * 4] =
                    make_float4(tf32r(u.x), tf32r(u.y), tf32r(u.z), tf32r(u.w));
            }
            __syncthreads();
        }
    }

    float* Tp = g_Tp[blockIdx.y];
#pragma unroll
    for (int mc = 0; mc < 2; mc++)
#pragma unroll
        for (int j = 0; j < 4; j++) {
            int row = m0 + wr * 32 + mc * 16 + g;
            int col = wc * 32 + j * 8 + tig * 2;
            *(float2*)&Tp[(size_t)row * 64 + col] =
                make_float2(acc[mc][j][0], acc[mc][j][1]);
            *(float2*)&Tp[(size_t)(row + 8) * 64 + col] =
                make_float2(acc[mc][j][2], acc[mc][j][3]);
        }
}

__global__ void __launch_bounds__(256) reduce_T() {
    int idx = (blockIdx.x * 256 + threadIdx.x) * 4;
    float4 s = *(const float4*)&g_Tp[0][idx];
#pragma unroll
    for (int c = 1; c < KSPLIT; c++) {
        float4 v = *(const float4*)&g_Tp[c][idx];
        s.x += v.x; s.y += v.y; s.z += v.z; s.w += v.w;
    }
    *(float4*)&g_T[idx] = s;
}

// ================= GEMM2: C = S^T @ T =================
__global__ void __launch_bounds__(256) gemm2_kernel(const float* __restrict__ S) {
    int b = blockIdx.x;
    int tid = threadIdx.x;
    int j4 = (tid & 15) * 4;
    int slice = tid >> 4;
    float4 acc = make_float4(0.f, 0.f, 0.f, 0.f);
    for (int k = slice; k < N_; k += 16) {
        float sb = __ldg(S + (size_t)k * 64 + b);
        float4 tv = *(const float4*)&g_T[(size_t)k * 64 + j4];
        acc.x += sb * tv.x; acc.y += sb * tv.y;
        acc.z += sb * tv.z; acc.w += sb * tv.w;
    }
    __shared__ float4 red[256];
    red[tid] = acc;
    __syncthreads();
    if (tid < 64) {
        int g = tid >> 2, comp = tid & 3;
        float v = 0.f;
#pragma unroll
        for (int sl = 0; sl < 16; sl++)
            v += ((const float*)&red[sl * 16 + g])[comp];
        g_C[b * 64 + tid] = v;
    }
}

// ========== finalize D: symmetrize, normalize, zero diagonal ==========
__global__ void __launch_bounds__(1024) finalizeD_kernel() {
    __shared__ float Dsm[4096];
    __shared__ float wred[32];
    __shared__ float mx_s;
    int tid = threadIdx.x;
    int lane = tid & 31, warp = tid >> 5;

    float lmax = -1e30f;
#pragma unroll
    for (int w = 0; w < 4; w++) {
        int p = tid + w * 1024;
        int i = p >> 6, jj = p & 63;
        float cs = 0.5f * (g_C[i * 64 + jj] + g_C[jj * 64 + i]);
        Dsm[p] = cs;
        lmax = fmaxf(lmax, cs);
    }
    for (int o = 16; o; o >>= 1) lmax = fmaxf(lmax, __shfl_xor_sync(~0u, lmax, o));
    if (lane == 0) wred[warp] = lmax;
    __syncthreads();
    if (warp == 0) {
        float v = wred[lane];
        for (int o = 16; o; o >>= 1) v = fmaxf(v, __shfl_xor_sync(~0u, v, o));
        if (lane == 0) mx_s = v;
    }
    __syncthreads();
    float inv = 1.0f / (mx_s + 1e-12f);
#pragma unroll
    for (int w = 0; w < 4; w++) {
        int p = tid + w * 1024;
        int i = p >> 6, jj = p & 63;
        float d = 1.0f - Dsm[p] * inv;
        g_D[p] = (i == jj) ? 0.0f : d;
    }
}

// ========== block 0: Prim MST ; blocks 1..64: death row i = bid-1 ==========
__global__ void __launch_bounds__(64) mstdeath_kernel() {
    __shared__ float Ds[64][65];
    __shared__ float mind[64];
    __shared__ int minu[64];
    int t = threadIdx.x;

    for (int q = 0; q < 64; q++)
        Ds[q][t] = g_D[q * 64 + t];
    __syncthreads();

    if (blockIdx.x == 0) {
        if (t < 32) {
            int lane = t;
            unsigned long long intree = 1ull;
#pragma unroll
            for (int h = 0; h < 2; h++) {
                int v = lane + 32 * h;
                mind[v] = Ds[0][v];
                minu[v] = 0;
            }
            __syncwarp();
            for (int step = 0; step < 63; step++) {
                float bval = BIGF; int bidx = 64;
#pragma unroll
                for (int h = 0; h < 2; h++) {
                    int v = lane + 32 * h;
                    float mv = ((intree >> v) & 1ull) ? BIGF : mind[v];
                    if (mv < bval || (mv == bval && v < bidx)) { bval = mv; bidx = v; }
                }
                for (int o = 16; o; o >>= 1) {
                    float ov = __shfl_xor_sync(~0u, bval, o);
                    int oi = __shfl_xor_sync(~0u, bidx, o);
                    if (ov < bval || (ov == bval && oi < bidx)) { bval = ov; bidx = oi; }
                }
                int vstar = bidx;
                if (lane == 0) { g_ws[step] = bval; g_us[step] = minu[vstar]; g_vs[step] = vstar; }
                intree |= (1ull << vstar);
#pragma unroll
                for (int h = 0; h < 2; h++) {
                    int v = lane + 32 * h;
                    float dv = Ds[vstar][v];
                    if (dv < mind[v]) { mind[v] = dv; minu[v] = vstar; }
                }
                __syncwarp();
            }
        }
    } else {
        int i = blockIdx.x - 1;
        int j = t;
        float pe = -1.0f;
        if (i < j) {
            float mm = BIGF;
#pragma unroll
            for (int k = 0; k < 64; k++) {
                float m2 = fmaxf(Ds[i][k], Ds[j][k]);
                if (k != i && k != j) mm = fminf(mm, m2);
            }
            float dij = Ds[i][j];
            pe = fmaxf(dij, mm) - dij;
        }
        g_pers[i * 64 + j] = pe;
    }
}

// ========== top-64 persistence pairs -> dgm1 ; dgm0 from MST weights ==========
__global__ void __launch_bounds__(1024) topk_kernel() {
    __shared__ float Dsm[4096];
    __shared__ float pers[4096];
    __shared__ unsigned long long msk[64];
    __shared__ float wmax[32];
    __shared__ int widx[32];

    int tid = threadIdx.x;
    int lane = tid & 31, warp = tid >> 5;

    if (tid < 64) {
        g_dgm0[2 * tid] = 0.0f;
        g_dgm0[2 * tid + 1] = (tid < 63) ? g_ws[tid] : 0.0f;
        msk[tid] = 0ull;
    }
    __syncthreads();
    if (tid < 63) {
        atomicOr(&msk[g_us[tid]], 1ull << g_vs[tid]);
        atomicOr(&msk[g_vs[tid]], 1ull << g_us[tid]);
    }
    __syncthreads();

#pragma unroll
    for (int w = 0; w < 4; w++) {
        int p = tid + w * 1024;
        int i = p >> 6, jj = p & 63;
        Dsm[p] = g_D[p];
        float pe = g_pers[p];
        if ((msk[i] >> jj) & 1ull) pe = -1.0f;
        pers[p] = pe;
    }
    __syncthreads();

    {
        float bv = -3e9f; int bi = 1 << 30;
#pragma unroll
        for (int q = 0; q < 4; q++) {
            int p = warp * 128 + q * 32 + lane;
            float v = pers[p];
            if (v > bv || (v == bv && p < bi)) { bv = v; bi = p; }
        }
        for (int o = 16; o; o >>= 1) {
            float ov = __shfl_xor_sync(~0u, bv, o);
            int oi = __shfl_xor_sync(~0u, bi, o);
            if (ov > bv || (ov == bv && oi < bi)) { bv = ov; bi = oi; }
        }
        if (lane == 0) { wmax[warp] = bv; widx[warp] = bi; }
    }
    __syncthreads();

    if (warp == 0) {
        for (int r = 0; r < 64; r++) {
            float v2 = wmax[lane]; int i2 = widx[lane]; int sg = lane;
            for (int o = 16; o; o >>= 1) {
                float ov = __shfl_xor_sync(~0u, v2, o);
                int oi = __shfl_xor_sync(~0u, i2, o);
                int os = __shfl_xor_sync(~0u, sg, o);
                if (ov > v2 || (ov == v2 && oi < i2)) { v2 = ov; i2 = oi; sg = os; }
            }
            if (lane == 0) {
                float b = 0.f, d = 0.f;
                if (v2 > 0.f) { b = Dsm[i2]; d = b + v2; }
                g_dgm1[2 * r] = b;
                g_dgm1[2 * r + 1] = d;
                pers[i2] = -4e9f;
            }
            __syncwarp();
            float nv = -3e9f; int ni = 1 << 30;
#pragma unroll
            for (int q = 0; q < 4; q++) {
                int p = sg * 128 + q * 32 + lane;
                float v = pers[p];
                if (v > nv || (v == nv && p < ni)) { nv = v; ni = p; }
            }
            for (int o = 16; o; o >>= 1) {
                float ov = __shfl_xor_sync(~0u, nv, o);
                int oi = __shfl_xor_sync(~0u, ni, o);
                if (ov > nv || (ov == nv && oi < ni)) { nv = ov; ni = oi; }
            }
            if (lane == 0) { wmax[sg] = nv; widx[sg] = ni; }
            __syncwarp();
        }
    }
}

// ====== Sinkhorn W1: 160 threads (5 warps), 2 threads/row, K in registers ======
// 33 terms per thread, 4-way accumulators (short dependency chains), one
// shfl_xor(1) combine, cheap 5-warp barrier. Phase A log-domain 20 iters;
// phase B multiplicative with K-refold every 20 + convergence early-exit.
__global__ void __launch_bounds__(160) sinkhorn_kernel(const float* __restrict__ Yb0,
                                                       const float* __restrict__ Yb1,
                                                       const float* __restrict__ Yn0,
                                                       const float* __restrict__ Yn1) {
    __shared__ float Cs[65][66];   // C * INV_EPS, col 65 padded 1e30
    __shared__ float Ct[65][66];   // transpose, col 65 padded 1e30
    __shared__ float Fsh[66], Gsh[66], Ush[66], Vsh[66];
    __shared__ float asum[160];
    __shared__ int notconv;

    int b = blockIdx.x;
    const float* X = (b & 1) ? g_dgm1 : g_dgm0;
    const float* Y = (b == 0) ? Yb0 : (b == 1) ? Yb1 : (b == 2) ? Yn0 : Yn1;
    int t = threadIdx.x;

    for (int idx = t; idx < 65 * 66; idx += 160) {
        int i = idx / 66, j = idx - i * 66;
        float v;
        if (j >= 65) v = 1e30f;
        else if (i < 64 && j < 64)
            v = fmaxf(fabsf(X[2 * i] - Y[2 * j]), fabsf(X[2 * i + 1] - Y[2 * j + 1])) * INV_EPS;
        else if (i < 64)
            v = 0.5f * (X[2 * i + 1] - X[2 * i]) * INV_EPS;
        else if (j < 64)
            v = 0.5f * (Y[2 * j + 1] - Y[2 * j]) * INV_EPS;
        else
            v = 0.f;
        Cs[i][j] = v;
    }
    if (t == 0) notconv = 0;
    __syncthreads();
    for (int idx = t; idx < 65 * 66; idx += 160) {
        int i = idx / 66, j = idx - i * 66;
        Ct[i][j] = (j < 65) ? Cs[j][i] : 1e30f;
    }
    if (t < 66) { Fsh[t] = 0.f; Gsh[t] = 0.f; }
    __syncthreads();

    int row = t >> 1; if (row > 64) row = 64;
    int sub = t & 1;
    bool act = (t < 130);
    bool lead = act && (sub == 0);
    float la = (row == 64) ? LOG64 : 0.f;
    float ela = (row == 64) ? 64.f : 1.f;
    int jb = sub * 33;                 // this thread's 33-column window

    float csr[33], csc[33];
#pragma unroll
    for (int s = 0; s < 33; s++) {
        csr[s] = Cs[row][jb + s];
        csc[s] = Ct[row][jb + s];
    }
    float tF = 0.f, tG = 0.f;

    // ---- phase A: log-domain (stabilizing) ----
    for (int it = 0; it < LOG_ITERS; it++) {
        {
            float s0 = 0.f, s1 = 0.f, s2 = 0.f, s3 = 0.f;
#pragma unroll
            for (int s = 0; s < 32; s += 4) {
                s0 += __expf(tF + Gsh[jb + s] - csr[s]);
                s1 += __expf(tF + Gsh[jb + s + 1] - csr[s + 1]);
                s2 += __expf(tF + Gsh[jb + s + 2] - csr[s + 2]);
                s3 += __expf(tF + Gsh[jb + s + 3] - csr[s + 3]);
            }
            s0 += __expf(tF + Gsh[jb + 32] - csr[32]);
            float s = (s0 + s1) + (s2 + s3);
            s += __shfl_xor_sync(~0u, s, 1);
            tF += la - __logf(s);
            if (lead) Fsh[row] = tF;
        }
        __syncthreads();
        {
            float s0 = 0.f, s1 = 0.f, s2 = 0.f, s3 = 0.f;
#pragma unroll
            for (int s = 0; s < 32; s += 4) {
                s0 += __expf(tG + Fsh[jb + s] - csc[s]);
                s1 += __expf(tG + Fsh[jb + s + 1] - csc[s + 1]);
                s2 += __expf(tG + Fsh[jb + s + 2] - csc[s + 2]);
                s3 += __expf(tG + Fsh[jb + s + 3] - csc[s + 3]);
            }
            s0 += __expf(tG + Fsh[jb + 32] - csc[32]);
            float s = (s0 + s1) + (s2 + s3);
            s += __shfl_xor_sync(~0u, s, 1);
            tG += la - __logf(s);
            if (lead) Gsh[row] = tG;
        }
        __syncthreads();
    }

    // ---- snapshot K into registers ----
    float kr[33], kc[33];
#pragma unroll
    for (int s = 0; s < 33; s++) {
        kr[s] = __expf(tF + Gsh[jb + s] - csr[s]);   // pads -> 0
        kc[s] = __expf(tG + Fsh[jb + s] - csc[s]);
    }
    __syncthreads();
    if (t < 66) { Ush[t] = 1.f; Vsh[t] = 1.f; }
    __syncthreads();

    // ---- phase B: multiplicative with folds + early exit ----
    const int BITERS = SINK_ITERS - LOG_ITERS;
    for (int it = 0; it < BITERS; it++) {
        {
            float s0 = 0.f, s1 = 0.f, s2 = 0.f, s3 = 0.f;
#pragma unroll
            for (int s = 0; s < 32; s += 4) {
                s0 += kr[s] * Vsh[jb + s];
                s1 += kr[s + 1] * Vsh[jb + s + 1];
                s2 += kr[s + 2] * Vsh[jb + s + 2];
                s3 += kr[s + 3] * Vsh[jb + s + 3];
            }
            s0 += kr[32] * Vsh[jb + 32];
            float s = (s0 + s1) + (s2 + s3);
            s += __shfl_xor_sync(~0u, s, 1);
            if (lead) Ush[row] = ela / s;
        }
        __syncthreads();
        {
            float s0 = 0.f, s1 = 0.f, s2 = 0.f, s3 = 0.f;
#pragma unroll
            for (int s = 0; s < 32; s += 4) {
                s0 += kc[s] * Ush[jb + s];
                s1 += kc[s + 1] * Ush[jb + s + 1];
                s2 += kc[s + 2] * Ush[jb + s + 2];
                s3 += kc[s + 3] * Ush[jb + s + 3];
            }
            s0 += kc[32] * Ush[jb + 32];
            float s = (s0 + s1) + (s2 + s3);
            s += __shfl_xor_sync(~0u, s, 1);
            if (lead) Vsh[row] = ela / s;
        }
        __syncthreads();

        if ((it % FOLD_EVERY) == (FOLD_EVERY - 1) && it != BITERS - 1) {
            if (lead) {
                float du = fabsf(Ush[row] - 1.f) + fabsf(Vsh[row] - 1.f);
                if (du > 1e-5f) atomicOr(&notconv, 1);
            }
            __syncthreads();
            int nc = notconv;
            float ur = Ush[row], vr = Vsh[row];
#pragma unroll
            for (int s = 0; s < 33; s++) {
                kr[s] *= ur * Vsh[jb + s];
                kc[s] *= vr * Ush[jb + s];
            }
            __syncthreads();
            if (t < 66) { Ush[t] = 1.f; Vsh[t] = 1.f; }
            if (t == 0) notconv = 0;
            __syncthreads();
            if (!nc) break;
        }
    }

    // loss = sum P*C ; P_ij = kr * u_i * v_j ; C = csr * EPSV (kr=0 kills pads)
    float acc = 0.f;
    if (act) {
        float ur = Ush[row];
        float a0 = 0.f, a1 = 0.f;
#pragma unroll
        for (int s = 0; s < 32; s += 2) {
            a0 += kr[s] * Vsh[jb + s] * csr[s];
            a1 += kr[s + 1] * Vsh[jb + s + 1] * csr[s + 1];
        }
        a0 += kr[32] * Vsh[jb + 32] * csr[32];
        acc = (a0 + a1) * ur * EPSV;
    }
    asum[t] = acc;
    __syncthreads();
    if (t == 0) {
        float s = 0.f;
        for (int q = 0; q < 130; q++) s += asum[q];
        g_loss[b] = s;
    }
}

__global__ void final_kernel(float* out) {
    out[0] = 0.1f * (g_loss[0] + g_loss[1] + g_loss[2] + g_loss[3]);
}

// ---------------- launch ----------------
extern "C" void kernel_launch(void* const* d_in, const int* in_sizes, int n_in,
                              void* d_out, int out_size) {
    const float* adj = (const float*)d_in[0];
    const float* S = (const float*)d_in[1];
    cudaFuncSetAttribute(gemm1_tc, cudaFuncAttributeMaxDynamicSharedMemorySize, GEMM1_SMEM);
    dim3 g1grid(128, KSPLIT);
    gemm1_tc<<<g1grid, 128, GEMM1_SMEM>>>(adj, S);
    reduce_T<<<(N_ * K_ / 4) / 256, 256>>>();
    gemm2_kernel<<<64, 256>>>(S);
    finalizeD_kernel<<<1, 1024>>>();
    mstdeath_kernel<<<65, 64>>>();
    topk_kernel<<<1, 1024>>>();
    sinkhorn_kernel<<<4, 160>>>((const float*)d_in[2], (const float*)d_in[3],
                                (const float*)d_in[4], (const float*)d_in[5]);
    final_kernel<<<1, 1>>>((float*)d_out);
}